// round 5
// baseline (speedup 1.0000x reference)
#include <cuda_runtime.h>

// MKMMD loss, fused persistent kernel (R5: 64x64 tiles, 4x4 pairs/thread to
// fix the LDS-crossbar bound; 36 tiles x 8 D-slices = 288 CTAs, 2/SM).
// total = concat(src,tgt): N=512 rows, D=512.
// result = (10*N + 2*sum_{i<j} s_i s_j (kL2+kL1)) / B^2, s=+/-1 by half.
// bw_x = 2*S_upper_x/(N^2-N)/100 ; k = sum_{m=0..4} exp(-d/(bw*10^m))

#define DDIM   512
#define TSZ    64
#define NTIL   8
#define NTILES 36
#define NSLICE 8
#define GRID   288
#define SW     68    // 272B row stride (4*17: odd 16B units), 16B-aligned .128

typedef unsigned long long u64;

__device__ float  g_p1[GRID];
__device__ float  g_p2[GRID];
__device__ float  g_p3[GRID];
__device__ float2 g_slab[NSLICE][NTILES][TSZ * TSZ];   // {l1,l2} per pair
__device__ int    g_bar1;
__device__ int    g_bar2;

__device__ __forceinline__ u64 add2(u64 a, u64 b) {
    u64 r; asm("add.rn.f32x2 %0,%1,%2;" : "=l"(r) : "l"(a), "l"(b)); return r;
}
__device__ __forceinline__ u64 fma2(u64 a, u64 b, u64 c) {
    u64 r; asm("fma.rn.f32x2 %0,%1,%2,%3;" : "=l"(r) : "l"(a), "l"(b), "l"(c)); return r;
}
__device__ __forceinline__ float lo2(u64 a) { return __uint_as_float((unsigned)(a & 0xffffffffu)); }
__device__ __forceinline__ float hi2(u64 a) { return __uint_as_float((unsigned)(a >> 32)); }

// block reduce; valid result on thread 0 only
__device__ __forceinline__ float bred(float v, float* sbuf) {
    const int tid = threadIdx.x;
#pragma unroll
    for (int o = 16; o; o >>= 1) v += __shfl_down_sync(0xffffffffu, v, o);
    __syncthreads();
    if ((tid & 31) == 0) sbuf[tid >> 5] = v;
    __syncthreads();
    float r = 0.0f;
    if (tid == 0) {
#pragma unroll
        for (int w = 0; w < 8; ++w) r += sbuf[w];
    }
    return r;
}

__global__ __launch_bounds__(256, 2) void mkmmd_kernel(
    const float* __restrict__ src, const float* __restrict__ tgt,
    float* __restrict__ out)
{
    __shared__ __align__(16) float As[TSZ][SW];
    __shared__ __align__(16) float Bs[TSZ][SW];   // NEGATED B rows
    __shared__ float sbuf[8];
    __shared__ float siv[10];

    const int tid = threadIdx.x;
    const int tx = tid & 15;
    const int ty = tid >> 4;

    const int tile  = blockIdx.x >> 3;   // 0..35
    const int slice = blockIdx.x & 7;    // 0..7 (64-wide D slice)

    // decode upper-triangle tile (ti <= tj) over 8x8 grid
    int t = tile, ti = 0;
    while (t >= NTIL - ti) { t -= NTIL - ti; ti++; }
    const int tj = ti + t;
    const int i0 = ti * TSZ, j0 = tj * TSZ;
    const float* Ap = (i0 < 256) ? src + (size_t)i0 * DDIM : tgt + (size_t)(i0 - 256) * DDIM;
    const float* Bp = (j0 < 256) ? src + (size_t)j0 * DDIM : tgt + (size_t)(j0 - 256) * DDIM;
    const int kb0 = slice * TSZ;

    // ---- load 64x64 slice of A and (negated) B, one shot ----
    {
        const int lr = tid >> 4;
        const int lc = (tid & 15) * 4;
#pragma unroll
        for (int m = 0; m < 4; ++m) {
            const int r = lr + 16 * m;
            float4 a = *(const float4*)(Ap + (size_t)r * DDIM + kb0 + lc);
            float4 b = *(const float4*)(Bp + (size_t)r * DDIM + kb0 + lc);
            *(float4*)&As[r][lc] = a;
            *(float4*)&Bs[r][lc] = make_float4(-b.x, -b.y, -b.z, -b.w);
        }
    }
    __syncthreads();

    // ---- 4x4-pair accumulation over 64 k (16 groups of 4 k) ----
    u64 l1a[4][4], l2a[4][4];
#pragma unroll
    for (int u = 0; u < 4; ++u)
#pragma unroll
        for (int v = 0; v < 4; ++v) { l1a[u][v] = 0ull; l2a[u][v] = 0ull; }

#pragma unroll 4
    for (int q = 0; q < 16; ++q) {
        ulonglong2 A[4], B[4];
#pragma unroll
        for (int u = 0; u < 4; ++u)
            A[u] = ((const ulonglong2*)&As[ty + 16 * u][0])[q];
#pragma unroll
        for (int v = 0; v < 4; ++v)
            B[v] = ((const ulonglong2*)&Bs[tx + 16 * v][0])[q];
#pragma unroll
        for (int h = 0; h < 2; ++h) {
            u64 av[4], bv[4];
#pragma unroll
            for (int u = 0; u < 4; ++u) av[u] = h ? A[u].y : A[u].x;
#pragma unroll
            for (int v = 0; v < 4; ++v) bv[v] = h ? B[v].y : B[v].x;
#pragma unroll
            for (int u = 0; u < 4; ++u)
#pragma unroll
                for (int v = 0; v < 4; ++v) {
                    u64 d  = add2(av[u], bv[v]);          // a - b (b pre-negated)
                    u64 ad = d & 0x7fffffff7fffffffULL;   // packed |d| (alu pipe)
                    l2a[u][v] = fma2(d, d, l2a[u][v]);
                    l1a[u][v] = add2(l1a[u][v], ad);
                }
        }
    }

    // ---- collapse halves; slab write; masked partial sums for bandwidth ----
    float s1 = 0.0f, s2 = 0.0f;
#pragma unroll
    for (int u = 0; u < 4; ++u) {
        const int il = ty + 16 * u;
#pragma unroll
        for (int v = 0; v < 4; ++v) {
            const int jl = tx + 16 * v;
            float l1 = lo2(l1a[u][v]) + hi2(l1a[u][v]);
            float l2 = lo2(l2a[u][v]) + hi2(l2a[u][v]);
            g_slab[slice][tile][il * TSZ + jl] = make_float2(l1, l2);
            if (ti < tj || jl > il) { s1 += l1; s2 += l2; }
        }
    }

    {
        float r1 = bred(s1, sbuf);
        float r2 = bred(s2, sbuf);
        if (tid == 0) {
            g_p1[blockIdx.x] = r1;
            g_p2[blockIdx.x] = r2;
            __threadfence();
            atomicAdd(&g_bar1, 1);
            while (*(volatile int*)&g_bar1 < GRID) {}
            __threadfence();
        }
        __syncthreads();   // release whole CTA; all slabs + partials visible
    }

    // ---- bandwidth ladder from 288 partials (fixed order, deterministic) ----
    {
        float v1 = ((volatile float*)g_p1)[tid];
        float v2 = ((volatile float*)g_p2)[tid];
        if (tid < GRID - 256) {
            v1 += ((volatile float*)g_p1)[tid + 256];
            v2 += ((volatile float*)g_p2)[tid + 256];
        }
        float S1 = bred(v1, sbuf);
        float S2 = bred(v2, sbuf);
        if (tid == 0) {
            const float cc = 2.0f * 0.01f / 261632.0f;   // 2/(N^2-N)/100
            float iv1 = 1.0f / (S1 * cc);
            float iv2 = 1.0f / (S2 * cc);
#pragma unroll
            for (int m = 0; m < 5; ++m) {
                siv[m]     = iv1;
                siv[5 + m] = iv2;
                iv1 *= 0.1f;
                iv2 *= 0.1f;
            }
        }
        __syncthreads();
    }

    // ---- exp phase: this CTA owns pairs [512*slice, 512*slice+512) ----
    float acc = 0.0f;
#pragma unroll
    for (int w = 0; w < 2; ++w) {
        const int p = slice * 512 + w * 256 + tid;
        float l1 = 0.0f, l2 = 0.0f;
#pragma unroll
        for (int s = 0; s < NSLICE; ++s) {
            float2 h = g_slab[s][tile][p];
            l1 += h.x;
            l2 += h.y;
        }
        const int il = p >> 6, jl = p & 63;
        if (ti < tj || jl > il) {
            float kv = 0.0f;
#pragma unroll
            for (int m = 0; m < 5; ++m) {
                kv += __expf(-l1 * siv[m]);
                kv += __expf(-l2 * siv[5 + m]);
            }
            acc += kv;
        }
    }

    float atot = bred(acc, sbuf);
    if (tid == 0) {
        const float sgn = ((ti < 4) == (tj < 4)) ? 1.0f : -1.0f;
        g_p3[blockIdx.x] = sgn * atot;
        __threadfence();
        int r = atomicAdd(&g_bar2, 1);
        if (r == GRID - 1) {
            // last arriver: every CTA is past its bar1 spin -> safe to reset
            __threadfence();
            float s = 0.0f;
            for (int q = 0; q < GRID; ++q) s += ((volatile float*)g_p3)[q];
            out[0] = 5120.0f / 65536.0f + s * (2.0f / 65536.0f);
            g_bar1 = 0;
            g_bar2 = 0;
            __threadfence();
        }
    }
}

extern "C" void kernel_launch(void* const* d_in, const int* in_sizes, int n_in,
                              void* d_out, int out_size) {
    const float* src = (const float*)d_in[0];
    const float* tgt = (const float*)d_in[1];
    float* out = (float*)d_out;
    mkmmd_kernel<<<GRID, 256>>>(src, tgt, out);
}

// round 6
// speedup vs baseline: 1.0875x; 1.0875x over previous
#include <cuda_runtime.h>

// MKMMD loss, fused persistent kernel (R6: all-scalar fp32 math with free
// abs/neg source modifiers — discriminates the FFMA2 throughput hypothesis).
// Geometry as R5: 36 upper-tri 64x64 tiles x 8 D-slices = 288 CTAs, 2/SM.
// total = concat(src,tgt): N=512 rows, D=512.
// result = (10*N + 2*sum_{i<j} s_i s_j (kL2+kL1)) / B^2, s=+/-1 by half.
// bw_x = 2*S_upper_x/(N^2-N)/100 ; k = sum_{m=0..4} exp(-d/(bw*10^m))

#define DDIM   512
#define TSZ    64
#define NTIL   8
#define NTILES 36
#define NSLICE 8
#define GRID   288
#define SW     66    // 264B row stride = 33 x 8B: odd -> conflict-free LDS.64

__device__ float  g_p1[GRID];
__device__ float  g_p2[GRID];
__device__ float  g_p3[GRID];
__device__ float2 g_slab[NSLICE][NTILES][TSZ * TSZ];   // {l1,l2} per pair
__device__ int    g_bar1;
__device__ int    g_bar2;

// block reduce; valid result on thread 0 only
__device__ __forceinline__ float bred(float v, float* sbuf) {
    const int tid = threadIdx.x;
#pragma unroll
    for (int o = 16; o; o >>= 1) v += __shfl_down_sync(0xffffffffu, v, o);
    __syncthreads();
    if ((tid & 31) == 0) sbuf[tid >> 5] = v;
    __syncthreads();
    float r = 0.0f;
    if (tid == 0) {
#pragma unroll
        for (int w = 0; w < 8; ++w) r += sbuf[w];
    }
    return r;
}

__global__ __launch_bounds__(256, 2) void mkmmd_kernel(
    const float* __restrict__ src, const float* __restrict__ tgt,
    float* __restrict__ out)
{
    __shared__ __align__(8) float As[TSZ][SW];
    __shared__ __align__(8) float Bs[TSZ][SW];
    __shared__ float sbuf[8];
    __shared__ float siv[10];

    const int tid = threadIdx.x;
    const int tx = tid & 15;
    const int ty = tid >> 4;

    const int tile  = blockIdx.x >> 3;   // 0..35
    const int slice = blockIdx.x & 7;    // 0..7 (64-wide D slice)

    // decode upper-triangle tile (ti <= tj) over 8x8 grid
    int t = tile, ti = 0;
    while (t >= NTIL - ti) { t -= NTIL - ti; ti++; }
    const int tj = ti + t;
    const int i0 = ti * TSZ, j0 = tj * TSZ;
    const float* Ap = (i0 < 256) ? src + (size_t)i0 * DDIM : tgt + (size_t)(i0 - 256) * DDIM;
    const float* Bp = (j0 < 256) ? src + (size_t)j0 * DDIM : tgt + (size_t)(j0 - 256) * DDIM;
    const int kb0 = slice * TSZ;

    // ---- load 64x64 slice of A and B, one shot ----
    {
        const int lr = tid >> 4;
        const int lc = (tid & 15) * 4;
#pragma unroll
        for (int m = 0; m < 4; ++m) {
            const int r = lr + 16 * m;
            float4 a = *(const float4*)(Ap + (size_t)r * DDIM + kb0 + lc);
            float4 b = *(const float4*)(Bp + (size_t)r * DDIM + kb0 + lc);
            *(float2*)&As[r][lc]     = make_float2(a.x, a.y);
            *(float2*)&As[r][lc + 2] = make_float2(a.z, a.w);
            *(float2*)&Bs[r][lc]     = make_float2(b.x, b.y);
            *(float2*)&Bs[r][lc + 2] = make_float2(b.z, b.w);
        }
    }
    __syncthreads();

    // ---- 4x4-pair scalar accumulation over 64 k (32 groups of 2 k) ----
    float l1a[4][4], l2a[4][4];
#pragma unroll
    for (int u = 0; u < 4; ++u)
#pragma unroll
        for (int v = 0; v < 4; ++v) { l1a[u][v] = 0.0f; l2a[u][v] = 0.0f; }

#pragma unroll 8
    for (int q = 0; q < 32; ++q) {          // 2 k per q via LDS.64
        float2 A2[4], B2[4];
#pragma unroll
        for (int u = 0; u < 4; ++u)
            A2[u] = ((const float2*)&As[ty + 16 * u][0])[q];
#pragma unroll
        for (int v = 0; v < 4; ++v)
            B2[v] = ((const float2*)&Bs[tx + 16 * v][0])[q];
#pragma unroll
        for (int u = 0; u < 4; ++u)
#pragma unroll
            for (int v = 0; v < 4; ++v) {
                float d0 = A2[u].x - B2[v].x;          // FADD (neg mod)
                float d1 = A2[u].y - B2[v].y;
                l1a[u][v] += fabsf(d0);                // FADD (|src| mod)
                l2a[u][v] = fmaf(d0, d0, l2a[u][v]);   // FFMA
                l1a[u][v] += fabsf(d1);
                l2a[u][v] = fmaf(d1, d1, l2a[u][v]);
            }
    }

    // ---- slab write; masked partial sums for bandwidth ----
    float s1 = 0.0f, s2 = 0.0f;
#pragma unroll
    for (int u = 0; u < 4; ++u) {
        const int il = ty + 16 * u;
#pragma unroll
        for (int v = 0; v < 4; ++v) {
            const int jl = tx + 16 * v;
            g_slab[slice][tile][il * TSZ + jl] = make_float2(l1a[u][v], l2a[u][v]);
            if (ti < tj || jl > il) { s1 += l1a[u][v]; s2 += l2a[u][v]; }
        }
    }

    {
        float r1 = bred(s1, sbuf);
        float r2 = bred(s2, sbuf);
        if (tid == 0) {
            g_p1[blockIdx.x] = r1;
            g_p2[blockIdx.x] = r2;
            __threadfence();
            atomicAdd(&g_bar1, 1);
            while (*(volatile int*)&g_bar1 < GRID) {}
            __threadfence();
        }
        __syncthreads();   // release whole CTA; all slabs + partials visible
    }

    // ---- bandwidth ladder from 288 partials (fixed order, deterministic) ----
    {
        float v1 = ((volatile float*)g_p1)[tid];
        float v2 = ((volatile float*)g_p2)[tid];
        if (tid < GRID - 256) {
            v1 += ((volatile float*)g_p1)[tid + 256];
            v2 += ((volatile float*)g_p2)[tid + 256];
        }
        float S1 = bred(v1, sbuf);
        float S2 = bred(v2, sbuf);
        if (tid == 0) {
            const float cc = 2.0f * 0.01f / 261632.0f;   // 2/(N^2-N)/100
            float iv1 = 1.0f / (S1 * cc);
            float iv2 = 1.0f / (S2 * cc);
#pragma unroll
            for (int m = 0; m < 5; ++m) {
                siv[m]     = iv1;
                siv[5 + m] = iv2;
                iv1 *= 0.1f;
                iv2 *= 0.1f;
            }
        }
        __syncthreads();
    }

    // ---- exp phase: this CTA owns pairs [512*slice, 512*slice+512) ----
    float acc = 0.0f;
#pragma unroll
    for (int w = 0; w < 2; ++w) {
        const int p = slice * 512 + w * 256 + tid;
        float l1 = 0.0f, l2 = 0.0f;
#pragma unroll
        for (int s = 0; s < NSLICE; ++s) {
            float2 h = g_slab[s][tile][p];
            l1 += h.x;
            l2 += h.y;
        }
        const int il = p >> 6, jl = p & 63;
        if (ti < tj || jl > il) {
            float kv = 0.0f;
#pragma unroll
            for (int m = 0; m < 5; ++m) {
                kv += __expf(-l1 * siv[m]);
                kv += __expf(-l2 * siv[5 + m]);
            }
            acc += kv;
        }
    }

    float atot = bred(acc, sbuf);
    if (tid == 0) {
        const float sgn = ((ti < 4) == (tj < 4)) ? 1.0f : -1.0f;
        g_p3[blockIdx.x] = sgn * atot;
        __threadfence();
        int r = atomicAdd(&g_bar2, 1);
        if (r == GRID - 1) {
            // last arriver: every CTA is past its bar1 spin -> safe to reset
            __threadfence();
            float s = 0.0f;
            for (int q = 0; q < GRID; ++q) s += ((volatile float*)g_p3)[q];
            out[0] = 5120.0f / 65536.0f + s * (2.0f / 65536.0f);
            g_bar1 = 0;
            g_bar2 = 0;
            __threadfence();
        }
    }
}

extern "C" void kernel_launch(void* const* d_in, const int* in_sizes, int n_in,
                              void* d_out, int out_size) {
    const float* src = (const float*)d_in[0];
    const float* tgt = (const float*)d_in[1];
    float* out = (float*)d_out;
    mkmmd_kernel<<<GRID, 256>>>(src, tgt, out);
}

// round 7
// speedup vs baseline: 1.1954x; 1.0992x over previous
#include <cuda_runtime.h>

// MKMMD loss, fused persistent kernel (R7: 136 CTAs, one 32x32 tile each,
// full D=512, scalar fp32 math, distances register-resident across the
// device barrier -> no slab, exp from registers, parallel final sum).
// total = concat(src,tgt): N=512 rows, D=512.
// result = (10*N + 2*sum_{i<j} s_i s_j (kL2+kL1)) / B^2, s=+/-1 by half.
// bw_x = 2*S_upper_x/(N^2-N)/100 ; k = sum_{m=0..4} exp(-d/(bw*10^m))

#define DDIM  512
#define NTIL  16
#define GRID  136
#define CH    64
#define SW    66    // 264B row stride: odd 8B units -> conflict-free LDS.64

__device__ float g_p1[GRID];
__device__ float g_p2[GRID];
__device__ float g_p3[GRID];
__device__ int   g_bar1;
__device__ int   g_bar2;

// block reduce; valid result on thread 0 only
__device__ __forceinline__ float bred(float v, float* sbuf) {
    const int tid = threadIdx.x;
#pragma unroll
    for (int o = 16; o; o >>= 1) v += __shfl_down_sync(0xffffffffu, v, o);
    __syncthreads();
    if ((tid & 31) == 0) sbuf[tid >> 5] = v;
    __syncthreads();
    float r = 0.0f;
    if (tid == 0) {
#pragma unroll
        for (int w = 0; w < 8; ++w) r += sbuf[w];
    }
    return r;
}

__global__ __launch_bounds__(256, 1) void mkmmd_kernel(
    const float* __restrict__ src, const float* __restrict__ tgt,
    float* __restrict__ out)
{
    __shared__ __align__(8) float As[2][32][SW];
    __shared__ __align__(8) float Bs[2][32][SW];
    __shared__ float sbuf[8];
    __shared__ float siv[10];
    __shared__ int   winflag;

    const int tid = threadIdx.x;
    const int tx = tid & 15;
    const int ty = tid >> 4;

    // decode upper-triangle tile (ti <= tj) over 16x16 grid of 32x32 tiles
    int t = blockIdx.x, ti = 0;
    while (t >= NTIL - ti) { t -= NTIL - ti; ti++; }
    const int tj = ti + t;
    const int i0 = ti * 32, j0 = tj * 32;
    const float* Ap = (i0 < 256) ? src + (size_t)i0 * DDIM : tgt + (size_t)(i0 - 256) * DDIM;
    const float* Bp = (j0 < 256) ? src + (size_t)j0 * DDIM : tgt + (size_t)(j0 - 256) * DDIM;

    // load assignment: row lr (0..31), 8 cols at lc (two float4)
    const int lr = tid >> 3;
    const int lc = (tid & 7) * 8;

    float l1a[2][2] = {{0.f, 0.f}, {0.f, 0.f}};
    float l2a[2][2] = {{0.f, 0.f}, {0.f, 0.f}};

    float4 pa0 = *(const float4*)(Ap + (size_t)lr * DDIM + lc);
    float4 pa1 = *(const float4*)(Ap + (size_t)lr * DDIM + lc + 4);
    float4 pb0 = *(const float4*)(Bp + (size_t)lr * DDIM + lc);
    float4 pb1 = *(const float4*)(Bp + (size_t)lr * DDIM + lc + 4);

    const int NCHUNK = DDIM / CH;   // 8
    for (int c = 0; c < NCHUNK; ++c) {
        const int p = c & 1;
        // store prefetched chunk (float2 STS: 264B row stride is 8B-aligned)
        *(float2*)&As[p][lr][lc]     = make_float2(pa0.x, pa0.y);
        *(float2*)&As[p][lr][lc + 2] = make_float2(pa0.z, pa0.w);
        *(float2*)&As[p][lr][lc + 4] = make_float2(pa1.x, pa1.y);
        *(float2*)&As[p][lr][lc + 6] = make_float2(pa1.z, pa1.w);
        *(float2*)&Bs[p][lr][lc]     = make_float2(pb0.x, pb0.y);
        *(float2*)&Bs[p][lr][lc + 2] = make_float2(pb0.z, pb0.w);
        *(float2*)&Bs[p][lr][lc + 4] = make_float2(pb1.x, pb1.y);
        *(float2*)&Bs[p][lr][lc + 6] = make_float2(pb1.z, pb1.w);
        __syncthreads();   // also guarantees compute(c-1) done before next STS

        if (c < NCHUNK - 1) {
            const int kb = (c + 1) * CH;
            pa0 = *(const float4*)(Ap + (size_t)lr * DDIM + kb + lc);
            pa1 = *(const float4*)(Ap + (size_t)lr * DDIM + kb + lc + 4);
            pb0 = *(const float4*)(Bp + (size_t)lr * DDIM + kb + lc);
            pb1 = *(const float4*)(Bp + (size_t)lr * DDIM + kb + lc + 4);
        }

        // 2x2 pairs, scalar fp32; 32 q-groups of 2 k via LDS.64
#pragma unroll 8
        for (int q = 0; q < CH / 2; ++q) {
            float2 a0 = ((const float2*)&As[p][ty][0])[q];
            float2 a1 = ((const float2*)&As[p][ty + 16][0])[q];
            float2 b0 = ((const float2*)&Bs[p][tx][0])[q];
            float2 b1 = ((const float2*)&Bs[p][tx + 16][0])[q];
            float2 av[2] = {a0, a1}, bv[2] = {b0, b1};
#pragma unroll
            for (int u = 0; u < 2; ++u)
#pragma unroll
                for (int v = 0; v < 2; ++v) {
                    float d0 = av[u].x - bv[v].x;          // FADD (neg mod)
                    float d1 = av[u].y - bv[v].y;
                    l1a[u][v] += fabsf(d0);                // FADD (|src| mod)
                    l2a[u][v] = fmaf(d0, d0, l2a[u][v]);
                    l1a[u][v] += fabsf(d1);
                    l2a[u][v] = fmaf(d1, d1, l2a[u][v]);
                }
        }
    }

    // masked upper-triangle partial sums for bandwidth (distances stay in regs)
    bool keep[2][2];
    float s1 = 0.0f, s2 = 0.0f;
#pragma unroll
    for (int u = 0; u < 2; ++u)
#pragma unroll
        for (int v = 0; v < 2; ++v) {
            const int i = i0 + ty + 16 * u;
            const int j = j0 + tx + 16 * v;
            keep[u][v] = (ti < tj) || (j > i);
            if (keep[u][v]) { s1 += l1a[u][v]; s2 += l2a[u][v]; }
        }

    {
        float r1 = bred(s1, sbuf);
        float r2 = bred(s2, sbuf);
        if (tid == 0) {
            g_p1[blockIdx.x] = r1;
            g_p2[blockIdx.x] = r2;
            __threadfence();
            atomicAdd(&g_bar1, 1);
            while (*(volatile int*)&g_bar1 < GRID) {}
            __threadfence();
        }
        __syncthreads();   // release whole CTA; all partials visible
    }

    // bandwidth ladder from the 136 partials (fixed order -> deterministic)
    {
        float v1 = 0.0f, v2 = 0.0f;
        if (tid < GRID) {
            v1 = ((volatile float*)g_p1)[tid];
            v2 = ((volatile float*)g_p2)[tid];
        }
        float S1 = bred(v1, sbuf);
        float S2 = bred(v2, sbuf);
        if (tid == 0) {
            const float cc = 2.0f * 0.01f / 261632.0f;   // 2/(N^2-N)/100
            float iv1 = 1.0f / (S1 * cc);
            float iv2 = 1.0f / (S2 * cc);
#pragma unroll
            for (int m = 0; m < 5; ++m) {
                siv[m]     = iv1;
                siv[5 + m] = iv2;
                iv1 *= 0.1f;
                iv2 *= 0.1f;
            }
        }
        __syncthreads();
    }

    // exp phase straight from registers
    float acc = 0.0f;
#pragma unroll
    for (int u = 0; u < 2; ++u)
#pragma unroll
        for (int v = 0; v < 2; ++v) {
            if (keep[u][v]) {
                float kv = 0.0f;
#pragma unroll
                for (int m = 0; m < 5; ++m) {
                    kv += __expf(-l1a[u][v] * siv[m]);
                    kv += __expf(-l2a[u][v] * siv[5 + m]);
                }
                acc += kv;
            }
        }

    float atot = bred(acc, sbuf);
    if (tid == 0) {
        const float sgn = ((ti < 8) == (tj < 8)) ? 1.0f : -1.0f;
        g_p3[blockIdx.x] = sgn * atot;
        __threadfence();
        int r = atomicAdd(&g_bar2, 1);
        winflag = (r == GRID - 1);
    }
    __syncthreads();

    if (winflag) {
        // last-arriving CTA: everyone is past bar1 -> safe to finalize + reset
        float v = (tid < GRID) ? ((volatile float*)g_p3)[tid] : 0.0f;
        float s = bred(v, sbuf);
        if (tid == 0) {
            out[0] = 5120.0f / 65536.0f + s * (2.0f / 65536.0f);
            g_bar1 = 0;
            g_bar2 = 0;
            __threadfence();
        }
    }
}

extern "C" void kernel_launch(void* const* d_in, const int* in_sizes, int n_in,
                              void* d_out, int out_size) {
    const float* src = (const float*)d_in[0];
    const float* tgt = (const float*)d_in[1];
    float* out = (float*)d_out;
    mkmmd_kernel<<<GRID, 256>>>(src, tgt, out);
}

// round 9
// speedup vs baseline: 1.4858x; 1.2429x over previous
#include <cuda_runtime.h>
#include <cuda_fp16.h>

// MKMMD loss, fused persistent kernel (R9 = R8 with fixed bitcasts: half2
// mainloop, fp32 chunk flush). Skeleton from R7: 136 CTAs, one 32x32 pair
// tile each, full D=512, distances register-resident across device barrier.
// total = concat(src,tgt): N=512 rows, D=512.
// result = (10*N + 2*sum_{i<j} s_i s_j (kL2+kL1)) / B^2, s=+/-1 by half.
// bw_x = 2*S_upper_x/(N^2-N)/100 ; k = sum_{m=0..4} exp(-d/(bw*10^m))

#define DDIM  512
#define NTIL  16
#define GRID  136
#define CH    64          // k-values per chunk (fp16 accum chain length)
#define SWH   36          // row stride in half2 units: 144B = 9*16B (odd) ->
                          // conflict-free LDS.128, 16B-aligned rows

__device__ float g_p1[GRID];
__device__ float g_p2[GRID];
__device__ float g_p3[GRID];
__device__ int   g_bar1;
__device__ int   g_bar2;

// block reduce; valid result on thread 0 only
__device__ __forceinline__ float bred(float v, float* sbuf) {
    const int tid = threadIdx.x;
#pragma unroll
    for (int o = 16; o; o >>= 1) v += __shfl_down_sync(0xffffffffu, v, o);
    __syncthreads();
    if ((tid & 31) == 0) sbuf[tid >> 5] = v;
    __syncthreads();
    float r = 0.0f;
    if (tid == 0) {
#pragma unroll
        for (int w = 0; w < 8; ++w) r += sbuf[w];
    }
    return r;
}

__device__ __forceinline__ unsigned pk(float x, float y) {
    __half2 h = __floats2half2_rn(x, y);
    return *reinterpret_cast<unsigned*>(&h);
}
__device__ __forceinline__ __half2 uph(unsigned u) {
    return *reinterpret_cast<__half2*>(&u);
}

__global__ __launch_bounds__(256, 1) void mkmmd_kernel(
    const float* __restrict__ src, const float* __restrict__ tgt,
    float* __restrict__ out)
{
    __shared__ __align__(16) unsigned As[2][32][SWH];   // half2 elements
    __shared__ __align__(16) unsigned Bs[2][32][SWH];
    __shared__ float sbuf[8];
    __shared__ float siv[10];
    __shared__ int   winflag;

    const int tid = threadIdx.x;
    const int tx = tid & 15;
    const int ty = tid >> 4;

    // decode upper-triangle tile (ti <= tj) over 16x16 grid of 32x32 tiles
    int t = blockIdx.x, ti = 0;
    while (t >= NTIL - ti) { t -= NTIL - ti; ti++; }
    const int tj = ti + t;
    const int i0 = ti * 32, j0 = tj * 32;
    const float* Ap = (i0 < 256) ? src + (size_t)i0 * DDIM : tgt + (size_t)(i0 - 256) * DDIM;
    const float* Bp = (j0 < 256) ? src + (size_t)j0 * DDIM : tgt + (size_t)(j0 - 256) * DDIM;

    // load assignment: row lr (0..31), 8 floats (-> 4 half2) at lcf
    const int lr  = tid >> 3;
    const int lcf = (tid & 7) * 8;        // float offset within 64-wide chunk
    const int lch = (tid & 7) * 4;        // half2 offset in smem row

    float l1a[2][2] = {{0.f, 0.f}, {0.f, 0.f}};
    float l2a[2][2] = {{0.f, 0.f}, {0.f, 0.f}};

    float4 pa0 = *(const float4*)(Ap + (size_t)lr * DDIM + lcf);
    float4 pa1 = *(const float4*)(Ap + (size_t)lr * DDIM + lcf + 4);
    float4 pb0 = *(const float4*)(Bp + (size_t)lr * DDIM + lcf);
    float4 pb1 = *(const float4*)(Bp + (size_t)lr * DDIM + lcf + 4);

    const int NCHUNK = DDIM / CH;   // 8
    for (int c = 0; c < NCHUNK; ++c) {
        const int p = c & 1;
        // convert prefetched floats to half2, one STS.128 per matrix
        {
            uint4 ua = make_uint4(pk(pa0.x, pa0.y), pk(pa0.z, pa0.w),
                                  pk(pa1.x, pa1.y), pk(pa1.z, pa1.w));
            uint4 ub = make_uint4(pk(pb0.x, pb0.y), pk(pb0.z, pb0.w),
                                  pk(pb1.x, pb1.y), pk(pb1.z, pb1.w));
            *(uint4*)&As[p][lr][lch] = ua;
            *(uint4*)&Bs[p][lr][lch] = ub;
        }
        __syncthreads();   // also guarantees compute(c-1) done before next STS

        if (c < NCHUNK - 1) {
            const int kb = (c + 1) * CH;
            pa0 = *(const float4*)(Ap + (size_t)lr * DDIM + kb + lcf);
            pa1 = *(const float4*)(Ap + (size_t)lr * DDIM + kb + lcf + 4);
            pb0 = *(const float4*)(Bp + (size_t)lr * DDIM + kb + lcf);
            pb1 = *(const float4*)(Bp + (size_t)lr * DDIM + kb + lcf + 4);
        }

        // fp16 chunk accumulators (chain length 64 adds, values << 65504)
        __half2 h1[2][2], h2[2][2];
        const __half2 hz = __float2half2_rn(0.0f);
#pragma unroll
        for (int u = 0; u < 2; ++u)
#pragma unroll
            for (int v = 0; v < 2; ++v) { h1[u][v] = hz; h2[u][v] = hz; }

        const uint4* a0p = (const uint4*)&As[p][ty][0];
        const uint4* a1p = (const uint4*)&As[p][ty + 16][0];
        const uint4* b0p = (const uint4*)&Bs[p][tx][0];
        const uint4* b1p = (const uint4*)&Bs[p][tx + 16][0];

#pragma unroll
        for (int q = 0; q < CH / 8; ++q) {     // 8 k per q via LDS.128
            uint4 A0 = a0p[q], A1 = a1p[q], B0 = b0p[q], B1 = b1p[q];
            const unsigned au0[4] = {A0.x, A0.y, A0.z, A0.w};
            const unsigned au1[4] = {A1.x, A1.y, A1.z, A1.w};
            const unsigned bu0[4] = {B0.x, B0.y, B0.z, B0.w};
            const unsigned bu1[4] = {B1.x, B1.y, B1.z, B1.w};
#pragma unroll
            for (int h = 0; h < 4; ++h) {      // 2 k per h
                __half2 av[2] = {uph(au0[h]), uph(au1[h])};
                __half2 bv[2] = {uph(bu0[h]), uph(bu1[h])};
#pragma unroll
                for (int u = 0; u < 2; ++u)
#pragma unroll
                    for (int v = 0; v < 2; ++v) {
                        __half2 d = __hsub2(av[u], bv[v]);        // HADD2 (fma)
                        h1[u][v] = __hadd2(h1[u][v], __habs2(d)); // LOP3 + HADD2
                        h2[u][v] = __hfma2(d, d, h2[u][v]);       // HFMA2 (fma)
                    }
            }
        }

        // flush chunk accumulators to fp32
#pragma unroll
        for (int u = 0; u < 2; ++u)
#pragma unroll
            for (int v = 0; v < 2; ++v) {
                float2 f1 = __half22float2(h1[u][v]);
                float2 f2 = __half22float2(h2[u][v]);
                l1a[u][v] += f1.x + f1.y;
                l2a[u][v] += f2.x + f2.y;
            }
    }

    // masked upper-triangle partial sums for bandwidth (dist stay in regs)
    bool keep[2][2];
    float s1 = 0.0f, s2 = 0.0f;
#pragma unroll
    for (int u = 0; u < 2; ++u)
#pragma unroll
        for (int v = 0; v < 2; ++v) {
            const int i = i0 + ty + 16 * u;
            const int j = j0 + tx + 16 * v;
            keep[u][v] = (ti < tj) || (j > i);
            if (keep[u][v]) { s1 += l1a[u][v]; s2 += l2a[u][v]; }
        }

    {
        float r1 = bred(s1, sbuf);
        float r2 = bred(s2, sbuf);
        if (tid == 0) {
            g_p1[blockIdx.x] = r1;
            g_p2[blockIdx.x] = r2;
            __threadfence();
            atomicAdd(&g_bar1, 1);
            while (*(volatile int*)&g_bar1 < GRID) {}
            __threadfence();
        }
        __syncthreads();   // release whole CTA; all partials visible
    }

    // bandwidth ladder from the 136 partials (fixed order -> deterministic)
    {
        float v1 = 0.0f, v2 = 0.0f;
        if (tid < GRID) {
            v1 = ((volatile float*)g_p1)[tid];
            v2 = ((volatile float*)g_p2)[tid];
        }
        float S1 = bred(v1, sbuf);
        float S2 = bred(v2, sbuf);
        if (tid == 0) {
            const float cc = 2.0f * 0.01f / 261632.0f;   // 2/(N^2-N)/100
            float iv1 = 1.0f / (S1 * cc);
            float iv2 = 1.0f / (S2 * cc);
#pragma unroll
            for (int m = 0; m < 5; ++m) {
                siv[m]     = iv1;
                siv[5 + m] = iv2;
                iv1 *= 0.1f;
                iv2 *= 0.1f;
            }
        }
        __syncthreads();
    }

    // exp phase straight from registers
    float acc = 0.0f;
#pragma unroll
    for (int u = 0; u < 2; ++u)
#pragma unroll
        for (int v = 0; v < 2; ++v) {
            if (keep[u][v]) {
                float kv = 0.0f;
#pragma unroll
                for (int m = 0; m < 5; ++m) {
                    kv += __expf(-l1a[u][v] * siv[m]);
                    kv += __expf(-l2a[u][v] * siv[5 + m]);
                }
                acc += kv;
            }
        }

    float atot = bred(acc, sbuf);
    if (tid == 0) {
        const float sgn = ((ti < 8) == (tj < 8)) ? 1.0f : -1.0f;
        g_p3[blockIdx.x] = sgn * atot;
        __threadfence();
        int r = atomicAdd(&g_bar2, 1);
        winflag = (r == GRID - 1);
    }
    __syncthreads();

    if (winflag) {
        // last-arriving CTA: everyone is past bar1 -> safe to finalize + reset
        float v = (tid < GRID) ? ((volatile float*)g_p3)[tid] : 0.0f;
        float s = bred(v, sbuf);
        if (tid == 0) {
            out[0] = 5120.0f / 65536.0f + s * (2.0f / 65536.0f);
            g_bar1 = 0;
            g_bar2 = 0;
            __threadfence();
        }
    }
}

extern "C" void kernel_launch(void* const* d_in, const int* in_sizes, int n_in,
                              void* d_out, int out_size) {
    const float* src = (const float*)d_in[0];
    const float* tgt = (const float*)d_in[1];
    float* out = (float*)d_out;
    mkmmd_kernel<<<GRID, 256>>>(src, tgt, out);
}